// round 14
// baseline (speedup 1.0000x reference)
#include <cuda_runtime.h>
#include <cuda_fp16.h>
#include <cstdint>

// ---------------------------------------------------------------------------
// SR_GNN. Stages 3/5: fp16 mma.sync m16n8k16 (same 2^-11 significand as tf32).
// Stage 4: tf32 m16n8k8 (A = f32 adjacency, cvt at frag load) + exact skips.
// Shape: 128x128 block, 8 warps (2x4), warp tile 64x32, 2 CTAs/SM (R10 proven).
//   hidden = emb[x]            (f32 for gates + fp16 for stage3 A)
//   big    = hidden_h @ [w_in|w_out|w_hh]^T + bias
//            cols<256 -> ht (f32 tf32-rounded, transposed per batch); else gh
//   inputs = [A_lo@h_in+b_iah | A_hi@h_out+b_oah]  stored fp16
//   gi     = inputs_h @ w_ih^T + b_ih
//   out    = gates(gi, gh, hidden)
// ---------------------------------------------------------------------------

#define Bsz 512
#define Nn  200
#define Mrows (Bsz*Nn)                 // 102400
#define HT_HALF (512*128*200)

__device__ float  g_hidden  [(size_t)Mrows * 128];
__device__ __half g_hidden_h[(size_t)Mrows * 128];
__device__ float  g_ht      [(size_t)2 * HT_HALF];
__device__ float  g_gh      [(size_t)Mrows * 384];
__device__ __half g_inputs_h[(size_t)Mrows * 256];
__device__ float  g_gi      [(size_t)Mrows * 384];
__device__ __half g_W1h     [640 * 128];
__device__ __half g_W2h     [384 * 256];
__device__ float  g_bias1   [640];

// ---------------- helpers ----------------
__device__ __forceinline__ uint32_t smem_u32(const void* p) {
    uint32_t a;
    asm("{ .reg .u64 t; cvta.to.shared.u64 t, %1; cvt.u32.u64 %0, t; }" : "=r"(a) : "l"(p));
    return a;
}
__device__ __forceinline__ uint32_t cvt_tf32(float f) {
    uint32_t r;
    asm("cvt.rna.tf32.f32 %0, %1;" : "=r"(r) : "f"(f));
    return r;
}
__device__ __forceinline__ float round_tf32(float f) { return __uint_as_float(cvt_tf32(f)); }

__device__ __forceinline__ void mma8(float* d, const uint32_t* a, const uint32_t* b) {
    asm volatile("mma.sync.aligned.m16n8k8.row.col.f32.tf32.tf32.f32 "
        "{%0,%1,%2,%3}, {%4,%5,%6,%7}, {%8,%9}, {%0,%1,%2,%3};"
        : "+f"(d[0]), "+f"(d[1]), "+f"(d[2]), "+f"(d[3])
        : "r"(a[0]), "r"(a[1]), "r"(a[2]), "r"(a[3]), "r"(b[0]), "r"(b[1]));
}
__device__ __forceinline__ void mma16(float* d, const uint32_t* a, const uint32_t* b) {
    asm volatile("mma.sync.aligned.m16n8k16.row.col.f32.f16.f16.f32 "
        "{%0,%1,%2,%3}, {%4,%5,%6,%7}, {%8,%9}, {%0,%1,%2,%3};"
        : "+f"(d[0]), "+f"(d[1]), "+f"(d[2]), "+f"(d[3])
        : "r"(a[0]), "r"(a[1]), "r"(a[2]), "r"(a[3]), "r"(b[0]), "r"(b[1]));
}
#define CP_ASYNC(dst, src, sz) \
    asm volatile("cp.async.cg.shared.global [%0], [%1], 16, %2;" :: "r"(dst), "l"(src), "r"(sz))
#define CP_COMMIT()  asm volatile("cp.async.commit_group;" ::: "memory")
#define CP_WAIT(n)   asm volatile("cp.async.wait_group %0;" :: "n"(n) : "memory")

// ---------------- prep / gather ----------------
__global__ void prep_kernel(const float* __restrict__ w_in, const float* __restrict__ b_in,
                            const float* __restrict__ w_out, const float* __restrict__ b_out,
                            const float* __restrict__ w_ih,
                            const float* __restrict__ w_hh, const float* __restrict__ b_hh) {
    int idx = blockIdx.x * blockDim.x + threadIdx.x;
    if (idx < 640 * 128) {
        int j = idx / 128, k = idx % 128;
        float v;
        if (j < 128)      v = w_in [j * 128 + k];
        else if (j < 256) v = w_out[(j - 128) * 128 + k];
        else              v = w_hh [(j - 256) * 128 + k];
        g_W1h[idx] = __float2half_rn(v);
    } else if (idx < 640 * 128 + 384 * 256) {
        int t = idx - 640 * 128;
        g_W2h[t] = __float2half_rn(w_ih[t]);
    } else if (idx < 640 * 128 + 384 * 256 + 640) {
        int j = idx - 640 * 128 - 384 * 256;
        g_bias1[j] = (j < 128) ? b_in[j] : (j < 256) ? b_out[j - 128] : b_hh[j - 256];
    }
}

__global__ void gather_kernel(const int* __restrict__ x, const float* __restrict__ emb) {
    long long t = (long long)blockIdx.x * blockDim.x + threadIdx.x;
    const long long total4 = (long long)Mrows * 32;
    if (t >= total4) return;
    int m = (int)(t >> 5), c = (int)(t & 31);
    int v = __ldg(&x[m]);
    float4 e = ((const float4*)emb)[(long long)v * 32 + c];
    ((float4*)g_hidden)[t] = e;
    __half2 h01 = __floats2half2_rn(e.x, e.y);
    __half2 h23 = __floats2half2_rn(e.z, e.w);
    ((__half2*)g_hidden_h)[t * 2]     = h01;
    ((__half2*)g_hidden_h)[t * 2 + 1] = h23;
}

// ---------------------------------------------------------------------------
// fp16 GEMM (stages 3 & 5): block 128x128, K-chunk 32 (2 x k16 MMA steps),
// 4-stage cp.async pipeline, warp tile 64x32. Dims exact (no guards).
// MODE 1: stage3 (n<256 -> ht transposed tf32-rounded; else gh, cshift=256)
// MODE 0: stage5 (plain f32 store)
// ---------------------------------------------------------------------------
#define LDP2 40                          // halfs per smem row (conflict-free)
#define ATILE_H (128 * LDP2)             // 5120 halfs
#define STAGE_H (2 * ATILE_H)            // 10240 halfs = 20480 B
#define SMEM_BYTES_H (4 * STAGE_H * 2)   // 81920 B

__device__ __forceinline__ void load_stage_h(uint32_t sb, const __half* __restrict__ A, int lda,
                                             const __half* __restrict__ B, int ldb,
                                             int k0, int tid) {
    #pragma unroll
    for (int it = 0; it < 2; ++it) {
        int item = it * 256 + tid;
        int row = item >> 2, c8 = item & 3;
        CP_ASYNC(sb + (uint32_t)(row * LDP2 + c8 * 8) * 2,
                 A + (size_t)row * lda + k0 + c8 * 8, 16);
    }
    #pragma unroll
    for (int it = 0; it < 2; ++it) {
        int item = it * 256 + tid;
        int row = item >> 2, c8 = item & 3;
        CP_ASYNC(sb + (uint32_t)(ATILE_H + row * LDP2 + c8 * 8) * 2,
                 B + (size_t)row * ldb + k0 + c8 * 8, 16);
    }
}

template <int MODE>
__global__ __launch_bounds__(256, 2)
void hgemm(const __half* __restrict__ A, int lda,
           const __half* __restrict__ Bm, int ldb,
           const float* __restrict__ bias,
           float* __restrict__ C, int ldc, int cshift,
           float* __restrict__ ht, int K) {
    extern __shared__ __half smemh[];
    const uint32_t sbase = smem_u32(smemh);
    const int tid = threadIdx.x;
    const int wid = tid >> 5, lane = tid & 31;
    const int gid = lane >> 2, tig = lane & 3;
    const int wm0 = (wid >> 2) * 64;
    const int wn0 = (wid & 3) * 32;

    const int n0 = blockIdx.x * 128;
    const int m0 = blockIdx.y * 128;
    const __half* Asrc = A + (size_t)m0 * lda;
    const __half* Bsrc = Bm + (size_t)n0 * ldb;

    float acc[4][4][4];
    #pragma unroll
    for (int i = 0; i < 4; ++i)
        #pragma unroll
        for (int j = 0; j < 4; ++j)
            #pragma unroll
            for (int q = 0; q < 4; ++q) acc[i][j][q] = 0.f;

    const int nk = K / 32;                       // 4 (stage3) or 8 (stage5)
    load_stage_h(sbase, Asrc, lda, Bsrc, ldb, 0, tid);
    CP_COMMIT();
    load_stage_h(sbase + (uint32_t)STAGE_H * 2, Asrc, lda, Bsrc, ldb, 32, tid);
    CP_COMMIT();
    load_stage_h(sbase + (uint32_t)2 * STAGE_H * 2, Asrc, lda, Bsrc, ldb, 64, tid);
    CP_COMMIT();
    CP_WAIT(2);
    __syncthreads();

    for (int ck = 0; ck < nk; ++ck) {
        if (ck + 3 < nk) {
            load_stage_h(sbase + (uint32_t)((ck + 3) & 3) * STAGE_H * 2,
                         Asrc, lda, Bsrc, ldb, (ck + 3) * 32, tid);
            CP_COMMIT();
        }
        const __half* As = smemh + (ck & 3) * STAGE_H;
        const __half* Bs = As + ATILE_H;

        #pragma unroll
        for (int ks = 0; ks < 2; ++ks) {
            uint32_t af[4][4], bf[4][2];
            #pragma unroll
            for (int tm = 0; tm < 4; ++tm) {
                const __half* p = As + (wm0 + tm * 16 + gid) * LDP2 + ks * 16 + tig * 2;
                af[tm][0] = *(const uint32_t*)p;
                af[tm][1] = *(const uint32_t*)(p + 8 * LDP2);
                af[tm][2] = *(const uint32_t*)(p + 8);
                af[tm][3] = *(const uint32_t*)(p + 8 * LDP2 + 8);
            }
            #pragma unroll
            for (int tn = 0; tn < 4; ++tn) {
                const __half* p = Bs + (wn0 + tn * 8 + gid) * LDP2 + ks * 16 + tig * 2;
                bf[tn][0] = *(const uint32_t*)p;
                bf[tn][1] = *(const uint32_t*)(p + 8);
            }
            #pragma unroll
            for (int tm = 0; tm < 4; ++tm)
                #pragma unroll
                for (int tn = 0; tn < 4; ++tn)
                    mma16(acc[tm][tn], af[tm], bf[tn]);
        }

        if (ck + 3 < nk) { CP_WAIT(2); } else if (ck + 2 < nk) { CP_WAIT(1); } else { CP_WAIT(0); }
        __syncthreads();
    }

    // ---- epilogue ----
    #pragma unroll
    for (int tm = 0; tm < 4; ++tm) {
        #pragma unroll
        for (int half_m = 0; half_m < 2; ++half_m) {
            const int gm = m0 + wm0 + tm * 16 + gid + half_m * 8;
            #pragma unroll
            for (int tn = 0; tn < 4; ++tn) {
                const int cb = n0 + wn0 + tn * 8 + tig * 2;
                float v0 = acc[tm][tn][half_m * 2 + 0] + bias[cb];
                float v1 = acc[tm][tn][half_m * 2 + 1] + bias[cb + 1];
                if (MODE == 1 && n0 < 256) {
                    int b = gm / 200, i = gm - b * 200;
                    int half = cb >> 7, jj = cb & 127;
                    float* base = ht + (size_t)half * HT_HALF + (size_t)b * 25600;
                    base[jj * 200 + i]       = round_tf32(v0);
                    base[(jj + 1) * 200 + i] = round_tf32(v1);
                } else {
                    *(float2*)(C + (size_t)gm * ldc + (cb - cshift)) = make_float2(v0, v1);
                }
            }
        }
    }
}

// ---------------------------------------------------------------------------
// tf32 GEMM (stage 4, = R10 MODE2 + exact skips + fp16 output):
// inputs = [A_lo@h_in + b_iah | A_hi@h_out + b_oah], stored fp16.
// grid (2, 2, 512): x=half, y=m-tile, z=batch. K=200.
// ---------------------------------------------------------------------------
#define LDP 36
#define TILE_F (128 * LDP)
#define STAGE_F (2 * TILE_F)
#define SMEM_BYTES_T (3 * STAGE_F * 4)   // 110592 B

__device__ __forceinline__ void load_stage_t(uint32_t sb, const float* __restrict__ A, int lda,
                                             int a_rows, const float* __restrict__ B, int ldb,
                                             int k0, int K, int tid) {
    #pragma unroll
    for (int it = 0; it < 4; ++it) {
        int item = it * 256 + tid;
        int row = item >> 3, c4 = item & 7;
        int gk = k0 + c4 * 4;
        bool ok = (row < a_rows) && (gk < K);
        const float* src = ok ? (A + (long long)row * lda + gk) : A;
        CP_ASYNC(sb + (uint32_t)(row * LDP + c4 * 4) * 4, src, ok ? 16 : 0);
    }
    #pragma unroll
    for (int it = 0; it < 4; ++it) {
        int item = it * 256 + tid;
        int row = item >> 3, c4 = item & 7;
        int gk = k0 + c4 * 4;
        bool ok = (gk < K);
        const float* src = ok ? (B + (long long)row * ldb + gk) : B;
        CP_ASYNC(sb + (uint32_t)(TILE_F + row * LDP + c4 * 4) * 4, src, ok ? 16 : 0);
    }
}

__global__ __launch_bounds__(256, 2)
void tgemm4(const float* __restrict__ Amat, const float* __restrict__ Bht,
            const float* __restrict__ biasA, const float* __restrict__ biasB,
            __half* __restrict__ Ch) {
    extern __shared__ float smemf[];
    const uint32_t sbase = smem_u32(smemf);
    const int tid = threadIdx.x;
    const int wid = tid >> 5, lane = tid & 31;
    const int gid = lane >> 2, tig = lane & 3;
    const int wm0 = (wid >> 2) * 64;
    const int wn0 = (wid & 3) * 32;
    const int K = Nn;                     // 200

    const int half = blockIdx.x;
    const float* A = Amat + (long long)blockIdx.z * (Nn * 2 * Nn) + half * Nn;
    const float* Bm = Bht + (size_t)half * HT_HALF + (long long)blockIdx.z * 25600;
    const float* bias = half ? biasB : biasA;
    __half* Cb = Ch + (long long)blockIdx.z * ((long long)Nn * 256) + half * 128;

    const int m0 = blockIdx.y * 128;
    const float* Asrc = A + (long long)m0 * (2 * Nn);
    const int a_rows = (Nn - m0) < 128 ? (Nn - m0) : 128;   // 128 or 72

    float acc[4][4][4];
    #pragma unroll
    for (int i = 0; i < 4; ++i)
        #pragma unroll
        for (int j = 0; j < 4; ++j)
            #pragma unroll
            for (int q = 0; q < 4; ++q) acc[i][j][q] = 0.f;

    const int nk = (K + 31) / 32;         // 7
    load_stage_t(sbase, Asrc, 2 * Nn, a_rows, Bm, Nn, 0, K, tid);
    CP_COMMIT();
    load_stage_t(sbase + (uint32_t)STAGE_F * 4, Asrc, 2 * Nn, a_rows, Bm, Nn, 32, K, tid);
    CP_COMMIT();
    CP_WAIT(1);
    __syncthreads();

    for (int ck = 0; ck < nk; ++ck) {
        if (ck + 2 < nk) {
            load_stage_t(sbase + (uint32_t)((ck + 2) % 3) * STAGE_F * 4,
                         Asrc, 2 * Nn, a_rows, Bm, Nn, (ck + 2) * 32, K, tid);
            CP_COMMIT();
        }
        const float* As_f = smemf + (ck % 3) * STAGE_F;
        const float* Bs_f = As_f + TILE_F;
        const int k0 = ck * 32;

        #pragma unroll
        for (int ks = 0; ks < 4; ++ks) {
            if (k0 + ks * 8 < K) {                        // warp-uniform; exact (zfill)
                uint32_t af[4][4], bf[4][2];
                #pragma unroll
                for (int tm = 0; tm < 4; ++tm) {
                    if (wm0 + tm * 16 < a_rows) {         // warp-uniform; exact
                        const float* p = As_f + (wm0 + tm * 16 + gid) * LDP + ks * 8 + tig;
                        af[tm][0] = cvt_tf32(p[0]);
                        af[tm][1] = cvt_tf32(p[8 * LDP]);
                        af[tm][2] = cvt_tf32(p[4]);
                        af[tm][3] = cvt_tf32(p[8 * LDP + 4]);
                    }
                }
                #pragma unroll
                for (int tn = 0; tn < 4; ++tn) {
                    const float* p = Bs_f + (wn0 + tn * 8 + gid) * LDP + ks * 8 + tig;
                    bf[tn][0] = __float_as_uint(p[0]);
                    bf[tn][1] = __float_as_uint(p[4]);
                }
                #pragma unroll
                for (int tm = 0; tm < 4; ++tm) {
                    if (wm0 + tm * 16 < a_rows) {
                        #pragma unroll
                        for (int tn = 0; tn < 4; ++tn)
                            mma8(acc[tm][tn], af[tm], bf[tn]);
                    }
                }
            }
        }

        if (ck + 2 < nk) { CP_WAIT(2); } else if (ck + 1 < nk) { CP_WAIT(1); } else { CP_WAIT(0); }
        __syncthreads();
    }

    // ---- epilogue: fp16 store into inputs_h ----
    #pragma unroll
    for (int tm = 0; tm < 4; ++tm) {
        #pragma unroll
        for (int half_m = 0; half_m < 2; ++half_m) {
            const int gml = wm0 + tm * 16 + gid + half_m * 8;
            if (gml >= a_rows) continue;
            const int gm = m0 + gml;
            #pragma unroll
            for (int tn = 0; tn < 4; ++tn) {
                const int cb = wn0 + tn * 8 + tig * 2;
                float v0 = acc[tm][tn][half_m * 2 + 0] + bias[cb];
                float v1 = acc[tm][tn][half_m * 2 + 1] + bias[cb + 1];
                *(__half2*)(Cb + (size_t)gm * 256 + cb) = __floats2half2_rn(v0, v1);
            }
        }
    }
}

// ---------------- gates ----------------
__global__ void gates_kernel(float* __restrict__ out) {
    long long idx = (long long)blockIdx.x * blockDim.x + threadIdx.x;
    const long long total = (long long)Mrows * 128;
    if (idx >= total) return;
    int row = (int)(idx >> 7);
    int d   = (int)(idx & 127);

    const float* gi = g_gi + (long long)row * 384;
    const float* gh = g_gh + (long long)row * 384;
    float i_r = gi[d], i_i = gi[128 + d], i_n = gi[256 + d];
    float h_r = gh[d], h_i = gh[128 + d], h_n = gh[256 + d];
    float hid = g_hidden[(long long)row * 128 + d];

    float gate_input  = 1.f / (1.f + expf(-(i_i + h_i)));
    float gate_reset  = 1.f / (1.f + expf(-(i_r + h_r)));
    float gate_output = tanhf(i_n + gate_reset * h_n);
    out[idx] = gate_output + gate_input * (hid - gate_output);
}

// ---------------------------------------------------------------------------
extern "C" void kernel_launch(void* const* d_in, const int* in_sizes, int n_in,
                              void* d_out, int out_size) {
    const int*   x     = (const int*)  d_in[0];
    const float* Amat  = (const float*)d_in[1];
    const float* emb   = (const float*)d_in[2];
    const float* w_in  = (const float*)d_in[3];
    const float* b_in  = (const float*)d_in[4];
    const float* w_out = (const float*)d_in[5];
    const float* b_out = (const float*)d_in[6];
    const float* w_ih  = (const float*)d_in[7];
    const float* b_ih  = (const float*)d_in[8];
    const float* w_hh  = (const float*)d_in[9];
    const float* b_hh  = (const float*)d_in[10];
    const float* b_iah = (const float*)d_in[11];
    const float* b_oah = (const float*)d_in[12];
    float* out = (float*)d_out;

    void *p_hidden_h, *p_ht, *p_gh, *p_inputs_h, *p_gi, *p_W1h, *p_W2h, *p_bias1;
    cudaGetSymbolAddress(&p_hidden_h, g_hidden_h);
    cudaGetSymbolAddress(&p_ht,       g_ht);
    cudaGetSymbolAddress(&p_gh,       g_gh);
    cudaGetSymbolAddress(&p_inputs_h, g_inputs_h);
    cudaGetSymbolAddress(&p_gi,       g_gi);
    cudaGetSymbolAddress(&p_W1h,      g_W1h);
    cudaGetSymbolAddress(&p_W2h,      g_W2h);
    cudaGetSymbolAddress(&p_bias1,    g_bias1);

    cudaFuncSetAttribute(hgemm<0>, cudaFuncAttributeMaxDynamicSharedMemorySize, SMEM_BYTES_H);
    cudaFuncSetAttribute(hgemm<1>, cudaFuncAttributeMaxDynamicSharedMemorySize, SMEM_BYTES_H);
    cudaFuncSetAttribute(tgemm4,   cudaFuncAttributeMaxDynamicSharedMemorySize, SMEM_BYTES_T);

    // 1. prep (round weights to fp16 once)
    {
        int total = 640 * 128 + 384 * 256 + 640;
        prep_kernel<<<(total + 255) / 256, 256>>>(w_in, b_in, w_out, b_out, w_ih, w_hh, b_hh);
    }
    // 2. gather (f32 + fp16)
    {
        long long total4 = (long long)Mrows * 32;
        gather_kernel<<<(int)((total4 + 255) / 256), 256>>>(x, emb);
    }
    // 3. big = hidden_h @ W1h^T + bias1  (fp16 MMA; n<256 -> ht, else gh)
    hgemm<1><<<dim3(5, Mrows / 128, 1), 256, SMEM_BYTES_H>>>(
        (const __half*)p_hidden_h, 128,
        (const __half*)p_W1h, 128,
        (const float*)p_bias1,
        (float*)p_gh, 384, 256,
        (float*)p_ht, 128);
    // 4. inputs_h = [A_lo@h_in + b_iah | A_hi@h_out + b_oah]  (tf32 MMA)
    tgemm4<<<dim3(2, 2, Bsz), 256, SMEM_BYTES_T>>>(
        Amat, (const float*)p_ht, b_iah, b_oah, (__half*)p_inputs_h);
    // 5. gi = inputs_h @ W2h^T + b_ih  (fp16 MMA)
    hgemm<0><<<dim3(3, Mrows / 128, 1), 256, SMEM_BYTES_H>>>(
        (const __half*)p_inputs_h, 256,
        (const __half*)p_W2h, 256,
        b_ih,
        (float*)p_gi, 384, 0,
        nullptr, 256);
    // 6. gates
    {
        long long total = (long long)Mrows * 128;
        gates_kernel<<<(int)((total + 255) / 256), 256>>>(out);
    }
}

// round 15
// speedup vs baseline: 1.2638x; 1.2638x over previous
#include <cuda_runtime.h>
#include <cuda_fp16.h>
#include <cstdint>

// ---------------------------------------------------------------------------
// SR_GNN via mma.sync tf32 (HMMA) — R10 structure (proven 498us) with gi/gh
// stored fp16 (pure intermediates -> ~310MB less DRAM traffic).
//   hidden = emb[x]                       (exact + rounded copies)
//   big    = hidden_r @ [w_in|w_out|w_hh]^T + bias
//            cols<256 -> ht (transposed per batch, tf32-ROUNDED f32); else gh (fp16)
//   inputs = [A[:,:, :N]@h_in + b_iah | A[:,:,N:]@h_out + b_oah]  (tf32-ROUNDED f32)
//   gi     = inputs @ w_ih^T + b_ih      (fp16 store)
//   out    = gates(gi, gh, hidden)
// ---------------------------------------------------------------------------

#define Bsz 512
#define Nn  200
#define Mrows (Bsz*Nn)                 // 102400
#define HT_HALF (512*128*200)

__device__ float  g_hidden  [(size_t)Mrows * 128];
__device__ float  g_hidden_r[(size_t)Mrows * 128];
__device__ float  g_ht      [(size_t)2 * HT_HALF];
__device__ __half g_gh_h    [(size_t)Mrows * 384];
__device__ float  g_inputs  [(size_t)Mrows * 256];
__device__ __half g_gi_h    [(size_t)Mrows * 384];
__device__ float  g_W1      [640 * 128];
__device__ float  g_W2r     [384 * 256];
__device__ float  g_bias1   [640];

// ---------------- helpers ----------------
__device__ __forceinline__ uint32_t smem_u32(const void* p) {
    uint32_t a;
    asm("{ .reg .u64 t; cvta.to.shared.u64 t, %1; cvt.u32.u64 %0, t; }" : "=r"(a) : "l"(p));
    return a;
}
__device__ __forceinline__ uint32_t cvt_tf32(float f) {
    uint32_t r;
    asm("cvt.rna.tf32.f32 %0, %1;" : "=r"(r) : "f"(f));
    return r;
}
__device__ __forceinline__ float round_tf32(float f) { return __uint_as_float(cvt_tf32(f)); }

__device__ __forceinline__ void mma8(float* d, const uint32_t* a, const uint32_t* b) {
    asm volatile("mma.sync.aligned.m16n8k8.row.col.f32.tf32.tf32.f32 "
        "{%0,%1,%2,%3}, {%4,%5,%6,%7}, {%8,%9}, {%0,%1,%2,%3};"
        : "+f"(d[0]), "+f"(d[1]), "+f"(d[2]), "+f"(d[3])
        : "r"(a[0]), "r"(a[1]), "r"(a[2]), "r"(a[3]), "r"(b[0]), "r"(b[1]));
}
#define CP_ASYNC(dst, src, sz) \
    asm volatile("cp.async.cg.shared.global [%0], [%1], 16, %2;" :: "r"(dst), "l"(src), "r"(sz))
#define CP_COMMIT()  asm volatile("cp.async.commit_group;" ::: "memory")
#define CP_WAIT(n)   asm volatile("cp.async.wait_group %0;" :: "n"(n) : "memory")

// ---------------- prep / gather ----------------
__global__ void prep_kernel(const float* __restrict__ w_in, const float* __restrict__ b_in,
                            const float* __restrict__ w_out, const float* __restrict__ b_out,
                            const float* __restrict__ w_ih,
                            const float* __restrict__ w_hh, const float* __restrict__ b_hh) {
    int idx = blockIdx.x * blockDim.x + threadIdx.x;
    if (idx < 640 * 128) {
        int j = idx / 128, k = idx % 128;
        float v;
        if (j < 128)      v = w_in [j * 128 + k];
        else if (j < 256) v = w_out[(j - 128) * 128 + k];
        else              v = w_hh [(j - 256) * 128 + k];
        g_W1[idx] = round_tf32(v);
    } else if (idx < 640 * 128 + 384 * 256) {
        int t = idx - 640 * 128;
        g_W2r[t] = round_tf32(w_ih[t]);
    } else if (idx < 640 * 128 + 384 * 256 + 640) {
        int j = idx - 640 * 128 - 384 * 256;
        g_bias1[j] = (j < 128) ? b_in[j] : (j < 256) ? b_out[j - 128] : b_hh[j - 256];
    }
}

__global__ void gather_kernel(const int* __restrict__ x, const float* __restrict__ emb) {
    long long t = (long long)blockIdx.x * blockDim.x + threadIdx.x;
    const long long total4 = (long long)Mrows * 32;
    if (t >= total4) return;
    int m = (int)(t >> 5), c = (int)(t & 31);
    int v = __ldg(&x[m]);
    float4 e = ((const float4*)emb)[(long long)v * 32 + c];
    ((float4*)g_hidden)[t] = e;
    float4 r;
    r.x = round_tf32(e.x); r.y = round_tf32(e.y);
    r.z = round_tf32(e.z); r.w = round_tf32(e.w);
    ((float4*)g_hidden_r)[t] = r;
}

// ---------------------------------------------------------------------------
// tf32 mma.sync GEMM. block 128x128, K-chunk 32, 3-stage cp.async pipeline,
// 256 thr (8 warps 2x4), warp tile 64x32. NO branches in the mainloop.
// MODE 1: stage3 (n<256 -> ht f32 rounded transposed; else gh fp16)
// MODE 2: stage4 merged halves (cvt A frags; tf32-rounded f32 store)
// MODE 0: stage5 (fp16 store to gi)
// ---------------------------------------------------------------------------
#define LDP 36
#define TILE_F (128 * LDP)
#define STAGE_F (2 * TILE_F)
#define SMEM_BYTES (3 * STAGE_F * 4)    // 110592 B

__device__ __forceinline__ void load_stage(uint32_t sb, const float* __restrict__ A, int lda,
                                           int a_rows, const float* __restrict__ B, int ldb,
                                           int k0, int K, int tid) {
    #pragma unroll
    for (int it = 0; it < 4; ++it) {
        int item = it * 256 + tid;
        int row = item >> 3, c4 = item & 7;
        int gk = k0 + c4 * 4;
        bool ok = (row < a_rows) && (gk < K);
        const float* src = ok ? (A + (long long)row * lda + gk) : A;
        CP_ASYNC(sb + (uint32_t)(row * LDP + c4 * 4) * 4, src, ok ? 16 : 0);
    }
    #pragma unroll
    for (int it = 0; it < 4; ++it) {
        int item = it * 256 + tid;
        int row = item >> 3, c4 = item & 7;
        int gk = k0 + c4 * 4;
        bool ok = (gk < K);
        const float* src = ok ? (B + (long long)row * ldb + gk) : B;
        CP_ASYNC(sb + (uint32_t)(TILE_F + row * LDP + c4 * 4) * 4, src, ok ? 16 : 0);
    }
}

template <int MODE>
__global__ __launch_bounds__(256, 2)
void mma_gemm(const float* __restrict__ A, int lda, int Arows, long long sA,
              const float* __restrict__ Bm, int ldb, long long sB,
              const float* __restrict__ bias, const float* __restrict__ bias2,
              float* __restrict__ Cf, __half* __restrict__ Ch,
              int ldc, long long sC, int cshift,
              float* __restrict__ ht, int K) {
    extern __shared__ float smem[];
    const uint32_t sbase = smem_u32(smem);
    const int tid = threadIdx.x;
    const int wid = tid >> 5, lane = tid & 31;
    const int gid = lane >> 2, tig = lane & 3;
    const int wm0 = (wid >> 2) * 64;
    const int wn0 = (wid & 3) * 32;

    int n0;
    if (MODE == 2) {
        const int half = blockIdx.x;
        A   += (long long)blockIdx.z * sA + half * Nn;
        Bm  += (size_t)half * HT_HALF + (long long)blockIdx.z * sB;
        bias = half ? bias2 : bias;
        Cf  += (long long)blockIdx.z * sC + half * 128;
        n0 = 0;
    } else {
        A  += (long long)blockIdx.z * sA;
        Bm += (long long)blockIdx.z * sB;
        n0 = blockIdx.x * 128;
    }
    const int m0 = blockIdx.y * 128;
    const float* Asrc = A + (long long)m0 * lda;
    const float* Bsrc = Bm + (long long)n0 * ldb;
    const int a_rows = (Arows - m0) < 128 ? (Arows - m0) : 128;

    float acc[4][4][4];
    #pragma unroll
    for (int i = 0; i < 4; ++i)
        #pragma unroll
        for (int j = 0; j < 4; ++j)
            #pragma unroll
            for (int q = 0; q < 4; ++q) acc[i][j][q] = 0.f;

    const int nk = (K + 31) / 32;
    load_stage(sbase, Asrc, lda, a_rows, Bsrc, ldb, 0, K, tid);
    CP_COMMIT();
    if (nk > 1) {
        load_stage(sbase + (uint32_t)STAGE_F * 4, Asrc, lda, a_rows, Bsrc, ldb, 32, K, tid);
        CP_COMMIT();
    }

    int buf = 0;
    for (int ck = 0; ck < nk; ++ck) {
        if (ck + 2 < nk) {
            int nbuf = (buf + 2 >= 3) ? buf - 1 : buf + 2;
            load_stage(sbase + (uint32_t)nbuf * STAGE_F * 4,
                       Asrc, lda, a_rows, Bsrc, ldb, (ck + 2) * 32, K, tid);
            CP_COMMIT();
            CP_WAIT(2);
        } else if (ck + 1 < nk) {
            CP_WAIT(1);
        } else {
            CP_WAIT(0);
        }
        __syncthreads();

        const float* As_f = smem + buf * STAGE_F;
        const float* Bs_f = As_f + TILE_F;
        #pragma unroll
        for (int ks = 0; ks < 4; ++ks) {
            uint32_t af[4][4], bf[4][2];
            #pragma unroll
            for (int tm = 0; tm < 4; ++tm) {
                const float* p = As_f + (wm0 + tm * 16 + gid) * LDP + ks * 8 + tig;
                if (MODE == 2) {
                    af[tm][0] = cvt_tf32(p[0]);
                    af[tm][1] = cvt_tf32(p[8 * LDP]);
                    af[tm][2] = cvt_tf32(p[4]);
                    af[tm][3] = cvt_tf32(p[8 * LDP + 4]);
                } else {
                    af[tm][0] = __float_as_uint(p[0]);
                    af[tm][1] = __float_as_uint(p[8 * LDP]);
                    af[tm][2] = __float_as_uint(p[4]);
                    af[tm][3] = __float_as_uint(p[8 * LDP + 4]);
                }
            }
            #pragma unroll
            for (int tn = 0; tn < 4; ++tn) {
                const float* p = Bs_f + (wn0 + tn * 8 + gid) * LDP + ks * 8 + tig;
                bf[tn][0] = __float_as_uint(p[0]);
                bf[tn][1] = __float_as_uint(p[4]);
            }
            #pragma unroll
            for (int tm = 0; tm < 4; ++tm)
                #pragma unroll
                for (int tn = 0; tn < 4; ++tn)
                    mma8(acc[tm][tn], af[tm], bf[tn]);
        }
        __syncthreads();
        buf = (buf + 1 >= 3) ? 0 : buf + 1;
    }

    // ---- epilogue ----
    #pragma unroll
    for (int tm = 0; tm < 4; ++tm) {
        const int r0 = m0 + wm0 + tm * 16 + gid;
        #pragma unroll
        for (int half_m = 0; half_m < 2; ++half_m) {
            const int gm = r0 + half_m * 8;
            if (gm >= Arows) continue;
            #pragma unroll
            for (int tn = 0; tn < 4; ++tn) {
                const int cb = n0 + wn0 + tn * 8 + tig * 2;
                float v0 = acc[tm][tn][half_m * 2 + 0] + bias[cb];
                float v1 = acc[tm][tn][half_m * 2 + 1] + bias[cb + 1];
                if (MODE == 1) {
                    if (n0 < 256) {
                        int b = gm / 200, i = gm - b * 200;
                        int half = cb >> 7, jj = cb & 127;
                        float* base = ht + (size_t)half * HT_HALF + (size_t)b * 25600;
                        base[jj * 200 + i]       = round_tf32(v0);
                        base[(jj + 1) * 200 + i] = round_tf32(v1);
                    } else {
                        *(__half2*)(Ch + (size_t)gm * ldc + (cb - cshift)) =
                            __floats2half2_rn(v0, v1);
                    }
                } else if (MODE == 2) {
                    *(float2*)(Cf + (size_t)gm * ldc + cb) =
                        make_float2(round_tf32(v0), round_tf32(v1));
                } else {
                    *(__half2*)(Ch + (size_t)gm * ldc + cb) = __floats2half2_rn(v0, v1);
                }
            }
        }
    }
}

// ---------------- gates (fp16 gi/gh, 2 elems/thread) ----------------
__global__ void gates_kernel(float* __restrict__ out) {
    long long idx = (long long)blockIdx.x * blockDim.x + threadIdx.x;
    const long long total = (long long)Mrows * 64;
    if (idx >= total) return;
    int row = (int)(idx >> 6);
    int p   = (int)(idx & 63);            // half2 index; d = 2p

    const __half2* gi = (const __half2*)(g_gi_h + (size_t)row * 384);
    const __half2* gh = (const __half2*)(g_gh_h + (size_t)row * 384);
    float2 i_r = __half22float2(gi[p]);
    float2 i_i = __half22float2(gi[64 + p]);
    float2 i_n = __half22float2(gi[128 + p]);
    float2 h_r = __half22float2(gh[p]);
    float2 h_i = __half22float2(gh[64 + p]);
    float2 h_n = __half22float2(gh[128 + p]);
    float2 hid = ((const float2*)(g_hidden + (size_t)row * 128))[p];

    float2 o;
    {
        float gin = 1.f / (1.f + expf(-(i_i.x + h_i.x)));
        float grs = 1.f / (1.f + expf(-(i_r.x + h_r.x)));
        float got = tanhf(i_n.x + grs * h_n.x);
        o.x = got + gin * (hid.x - got);
    }
    {
        float gin = 1.f / (1.f + expf(-(i_i.y + h_i.y)));
        float grs = 1.f / (1.f + expf(-(i_r.y + h_r.y)));
        float got = tanhf(i_n.y + grs * h_n.y);
        o.y = got + gin * (hid.y - got);
    }
    ((float2*)(out + (size_t)row * 128))[p] = o;
}

// ---------------------------------------------------------------------------
extern "C" void kernel_launch(void* const* d_in, const int* in_sizes, int n_in,
                              void* d_out, int out_size) {
    const int*   x     = (const int*)  d_in[0];
    const float* Amat  = (const float*)d_in[1];
    const float* emb   = (const float*)d_in[2];
    const float* w_in  = (const float*)d_in[3];
    const float* b_in  = (const float*)d_in[4];
    const float* w_out = (const float*)d_in[5];
    const float* b_out = (const float*)d_in[6];
    const float* w_ih  = (const float*)d_in[7];
    const float* b_ih  = (const float*)d_in[8];
    const float* w_hh  = (const float*)d_in[9];
    const float* b_hh  = (const float*)d_in[10];
    const float* b_iah = (const float*)d_in[11];
    const float* b_oah = (const float*)d_in[12];
    float* out = (float*)d_out;

    void *p_hidden_r, *p_ht, *p_gh_h, *p_inputs, *p_gi_h, *p_W1, *p_W2r, *p_bias1;
    cudaGetSymbolAddress(&p_hidden_r, g_hidden_r);
    cudaGetSymbolAddress(&p_ht,     g_ht);
    cudaGetSymbolAddress(&p_gh_h,   g_gh_h);
    cudaGetSymbolAddress(&p_inputs, g_inputs);
    cudaGetSymbolAddress(&p_gi_h,   g_gi_h);
    cudaGetSymbolAddress(&p_W1,     g_W1);
    cudaGetSymbolAddress(&p_W2r,    g_W2r);
    cudaGetSymbolAddress(&p_bias1,  g_bias1);

    cudaFuncSetAttribute(mma_gemm<0>, cudaFuncAttributeMaxDynamicSharedMemorySize, SMEM_BYTES);
    cudaFuncSetAttribute(mma_gemm<1>, cudaFuncAttributeMaxDynamicSharedMemorySize, SMEM_BYTES);
    cudaFuncSetAttribute(mma_gemm<2>, cudaFuncAttributeMaxDynamicSharedMemorySize, SMEM_BYTES);

    // 1. prep
    {
        int total = 640 * 128 + 384 * 256 + 640;
        prep_kernel<<<(total + 255) / 256, 256>>>(w_in, b_in, w_out, b_out, w_ih, w_hh, b_hh);
    }
    // 2. gather
    {
        long long total4 = (long long)Mrows * 32;
        gather_kernel<<<(int)((total4 + 255) / 256), 256>>>(x, emb);
    }
    // 3. big = hidden_r @ W1^T + bias1  (n<256 -> ht f32 rounded; else gh fp16)
    mma_gemm<1><<<dim3(5, Mrows / 128, 1), 256, SMEM_BYTES>>>(
        (const float*)p_hidden_r, 128, Mrows, 0,
        (const float*)p_W1, 128, 0,
        (const float*)p_bias1, nullptr,
        nullptr, (__half*)p_gh_h, 384, 0, 256,
        (float*)p_ht, 128);
    // 4. inputs = [A_lo@h_in + b_iah | A_hi@h_out + b_oah]  (f32 rounded)
    mma_gemm<2><<<dim3(2, 2, Bsz), 256, SMEM_BYTES>>>(
        Amat, 2 * Nn, Nn, (long long)Nn * 2 * Nn,
        (const float*)p_ht, Nn, 25600,
        b_iah, b_oah,
        (float*)p_inputs, nullptr, 256, (long long)Nn * 256, 0,
        nullptr, Nn);
    // 5. gi = inputs @ w_ih^T + b_ih  (fp16 store)
    mma_gemm<0><<<dim3(3, Mrows / 128, 1), 256, SMEM_BYTES>>>(
        (const float*)p_inputs, 256, Mrows, 0,
        (const float*)p_W2r, 256, 0,
        b_ih, nullptr,
        nullptr, (__half*)p_gi_h, 384, 0, 0,
        nullptr, 256);
    // 6. gates
    {
        long long total = (long long)Mrows * 64;
        gates_kernel<<<(int)((total + 255) / 256), 256>>>(out);
    }
}

// round 16
// speedup vs baseline: 1.3710x; 1.0848x over previous
#include <cuda_runtime.h>
#include <cuda_fp16.h>
#include <cstdint>

// ---------------------------------------------------------------------------
// SR_GNN. Stages 3/5: tf32 mma (R15 proven). Stage 4: fp16 m16n8k16 mainloop
// (A = f32 adjacency cvt'd at frag load; B = ht stored fp16). gi/gh fp16.
//   hidden = emb[x]                       (exact + rounded copies)
//   big    = hidden_r @ [w_in|w_out|w_hh]^T + bias
//            cols<256 -> ht (transposed per batch, fp16); else gh (fp16)
//   inputs = [A_lo@h_in+b_iah | A_hi@h_out+b_oah]   (tf32-rounded f32)
//   gi     = inputs @ w_ih^T + b_ih       (fp16 store)
//   out    = gates(gi, gh, hidden)
// ---------------------------------------------------------------------------

#define Bsz 512
#define Nn  200
#define Mrows (Bsz*Nn)                 // 102400
#define HT_HALF (512*128*200)          // halfs per half-buffer

__device__ float  g_hidden  [(size_t)Mrows * 128];
__device__ float  g_hidden_r[(size_t)Mrows * 128];
__device__ __half g_ht_h    [(size_t)2 * HT_HALF];
__device__ __half g_gh_h    [(size_t)Mrows * 384];
__device__ float  g_inputs  [(size_t)Mrows * 256];
__device__ __half g_gi_h    [(size_t)Mrows * 384];
__device__ float  g_W1      [640 * 128];
__device__ float  g_W2r     [384 * 256];
__device__ float  g_bias1   [640];

// ---------------- helpers ----------------
__device__ __forceinline__ uint32_t smem_u32(const void* p) {
    uint32_t a;
    asm("{ .reg .u64 t; cvta.to.shared.u64 t, %1; cvt.u32.u64 %0, t; }" : "=r"(a) : "l"(p));
    return a;
}
__device__ __forceinline__ uint32_t cvt_tf32(float f) {
    uint32_t r;
    asm("cvt.rna.tf32.f32 %0, %1;" : "=r"(r) : "f"(f));
    return r;
}
__device__ __forceinline__ float round_tf32(float f) { return __uint_as_float(cvt_tf32(f)); }
__device__ __forceinline__ uint32_t pack_h2(float lo, float hi) {
    __half2 h = __floats2half2_rn(lo, hi);
    return *(uint32_t*)&h;
}

__device__ __forceinline__ void mma8(float* d, const uint32_t* a, const uint32_t* b) {
    asm volatile("mma.sync.aligned.m16n8k8.row.col.f32.tf32.tf32.f32 "
        "{%0,%1,%2,%3}, {%4,%5,%6,%7}, {%8,%9}, {%0,%1,%2,%3};"
        : "+f"(d[0]), "+f"(d[1]), "+f"(d[2]), "+f"(d[3])
        : "r"(a[0]), "r"(a[1]), "r"(a[2]), "r"(a[3]), "r"(b[0]), "r"(b[1]));
}
__device__ __forceinline__ void mma16(float* d, const uint32_t* a, const uint32_t* b) {
    asm volatile("mma.sync.aligned.m16n8k16.row.col.f32.f16.f16.f32 "
        "{%0,%1,%2,%3}, {%4,%5,%6,%7}, {%8,%9}, {%0,%1,%2,%3};"
        : "+f"(d[0]), "+f"(d[1]), "+f"(d[2]), "+f"(d[3])
        : "r"(a[0]), "r"(a[1]), "r"(a[2]), "r"(a[3]), "r"(b[0]), "r"(b[1]));
}
#define CP_ASYNC(dst, src, sz) \
    asm volatile("cp.async.cg.shared.global [%0], [%1], 16, %2;" :: "r"(dst), "l"(src), "r"(sz))
#define CP_COMMIT()  asm volatile("cp.async.commit_group;" ::: "memory")
#define CP_WAIT(n)   asm volatile("cp.async.wait_group %0;" :: "n"(n) : "memory")

// ---------------- prep / gather ----------------
__global__ void prep_kernel(const float* __restrict__ w_in, const float* __restrict__ b_in,
                            const float* __restrict__ w_out, const float* __restrict__ b_out,
                            const float* __restrict__ w_ih,
                            const float* __restrict__ w_hh, const float* __restrict__ b_hh) {
    int idx = blockIdx.x * blockDim.x + threadIdx.x;
    if (idx < 640 * 128) {
        int j = idx / 128, k = idx % 128;
        float v;
        if (j < 128)      v = w_in [j * 128 + k];
        else if (j < 256) v = w_out[(j - 128) * 128 + k];
        else              v = w_hh [(j - 256) * 128 + k];
        g_W1[idx] = round_tf32(v);
    } else if (idx < 640 * 128 + 384 * 256) {
        int t = idx - 640 * 128;
        g_W2r[t] = round_tf32(w_ih[t]);
    } else if (idx < 640 * 128 + 384 * 256 + 640) {
        int j = idx - 640 * 128 - 384 * 256;
        g_bias1[j] = (j < 128) ? b_in[j] : (j < 256) ? b_out[j - 128] : b_hh[j - 256];
    }
}

__global__ void gather_kernel(const int* __restrict__ x, const float* __restrict__ emb) {
    long long t = (long long)blockIdx.x * blockDim.x + threadIdx.x;
    const long long total4 = (long long)Mrows * 32;
    if (t >= total4) return;
    int m = (int)(t >> 5), c = (int)(t & 31);
    int v = __ldg(&x[m]);
    float4 e = ((const float4*)emb)[(long long)v * 32 + c];
    ((float4*)g_hidden)[t] = e;
    float4 r;
    r.x = round_tf32(e.x); r.y = round_tf32(e.y);
    r.z = round_tf32(e.z); r.w = round_tf32(e.w);
    ((float4*)g_hidden_r)[t] = r;
}

// ---------------------------------------------------------------------------
// tf32 GEMM (stages 3 & 5): identical to R15. block 128x128, K-chunk 32,
// 3-stage cp.async, warp tile 64x32. No mainloop branches.
// MODE 1: stage3 (n<256 -> ht fp16 transposed; else gh fp16, cshift=256)
// MODE 0: stage5 (fp16 store to gi)
// ---------------------------------------------------------------------------
#define LDP 36
#define TILE_F (128 * LDP)
#define STAGE_F (2 * TILE_F)
#define SMEM_BYTES (3 * STAGE_F * 4)    // 110592 B

__device__ __forceinline__ void load_stage(uint32_t sb, const float* __restrict__ A, int lda,
                                           int a_rows, const float* __restrict__ B, int ldb,
                                           int k0, int K, int tid) {
    #pragma unroll
    for (int it = 0; it < 4; ++it) {
        int item = it * 256 + tid;
        int row = item >> 3, c4 = item & 7;
        int gk = k0 + c4 * 4;
        bool ok = (row < a_rows) && (gk < K);
        const float* src = ok ? (A + (long long)row * lda + gk) : A;
        CP_ASYNC(sb + (uint32_t)(row * LDP + c4 * 4) * 4, src, ok ? 16 : 0);
    }
    #pragma unroll
    for (int it = 0; it < 4; ++it) {
        int item = it * 256 + tid;
        int row = item >> 3, c4 = item & 7;
        int gk = k0 + c4 * 4;
        bool ok = (gk < K);
        const float* src = ok ? (B + (long long)row * ldb + gk) : B;
        CP_ASYNC(sb + (uint32_t)(TILE_F + row * LDP + c4 * 4) * 4, src, ok ? 16 : 0);
    }
}

template <int MODE>
__global__ __launch_bounds__(256, 2)
void mma_gemm(const float* __restrict__ A, int lda, int Arows,
              const float* __restrict__ Bm, int ldb,
              const float* __restrict__ bias,
              __half* __restrict__ Ch, int ldc, int cshift,
              __half* __restrict__ ht, int K) {
    extern __shared__ float smem[];
    const uint32_t sbase = smem_u32(smem);
    const int tid = threadIdx.x;
    const int wid = tid >> 5, lane = tid & 31;
    const int gid = lane >> 2, tig = lane & 3;
    const int wm0 = (wid >> 2) * 64;
    const int wn0 = (wid & 3) * 32;

    const int n0 = blockIdx.x * 128;
    const int m0 = blockIdx.y * 128;
    const float* Asrc = A + (long long)m0 * lda;
    const float* Bsrc = Bm + (long long)n0 * ldb;
    const int a_rows = (Arows - m0) < 128 ? (Arows - m0) : 128;

    float acc[4][4][4];
    #pragma unroll
    for (int i = 0; i < 4; ++i)
        #pragma unroll
        for (int j = 0; j < 4; ++j)
            #pragma unroll
            for (int q = 0; q < 4; ++q) acc[i][j][q] = 0.f;

    const int nk = (K + 31) / 32;
    load_stage(sbase, Asrc, lda, a_rows, Bsrc, ldb, 0, K, tid);
    CP_COMMIT();
    load_stage(sbase + (uint32_t)STAGE_F * 4, Asrc, lda, a_rows, Bsrc, ldb, 32, K, tid);
    CP_COMMIT();

    int buf = 0;
    for (int ck = 0; ck < nk; ++ck) {
        if (ck + 2 < nk) {
            int nbuf = (buf + 2 >= 3) ? buf - 1 : buf + 2;
            load_stage(sbase + (uint32_t)nbuf * STAGE_F * 4,
                       Asrc, lda, a_rows, Bsrc, ldb, (ck + 2) * 32, K, tid);
            CP_COMMIT();
            CP_WAIT(2);
        } else if (ck + 1 < nk) {
            CP_WAIT(1);
        } else {
            CP_WAIT(0);
        }
        __syncthreads();

        const float* As_f = smem + buf * STAGE_F;
        const float* Bs_f = As_f + TILE_F;
        #pragma unroll
        for (int ks = 0; ks < 4; ++ks) {
            uint32_t af[4][4], bf[4][2];
            #pragma unroll
            for (int tm = 0; tm < 4; ++tm) {
                const float* p = As_f + (wm0 + tm * 16 + gid) * LDP + ks * 8 + tig;
                af[tm][0] = __float_as_uint(p[0]);
                af[tm][1] = __float_as_uint(p[8 * LDP]);
                af[tm][2] = __float_as_uint(p[4]);
                af[tm][3] = __float_as_uint(p[8 * LDP + 4]);
            }
            #pragma unroll
            for (int tn = 0; tn < 4; ++tn) {
                const float* p = Bs_f + (wn0 + tn * 8 + gid) * LDP + ks * 8 + tig;
                bf[tn][0] = __float_as_uint(p[0]);
                bf[tn][1] = __float_as_uint(p[4]);
            }
            #pragma unroll
            for (int tm = 0; tm < 4; ++tm)
                #pragma unroll
                for (int tn = 0; tn < 4; ++tn)
                    mma8(acc[tm][tn], af[tm], bf[tn]);
        }
        __syncthreads();
        buf = (buf + 1 >= 3) ? 0 : buf + 1;
    }

    // ---- epilogue ----
    #pragma unroll
    for (int tm = 0; tm < 4; ++tm) {
        const int r0 = m0 + wm0 + tm * 16 + gid;
        #pragma unroll
        for (int half_m = 0; half_m < 2; ++half_m) {
            const int gm = r0 + half_m * 8;
            if (gm >= Arows) continue;
            #pragma unroll
            for (int tn = 0; tn < 4; ++tn) {
                const int cb = n0 + wn0 + tn * 8 + tig * 2;
                float v0 = acc[tm][tn][half_m * 2 + 0] + bias[cb];
                float v1 = acc[tm][tn][half_m * 2 + 1] + bias[cb + 1];
                if (MODE == 1 && n0 < 256) {
                    int b = gm / 200, i = gm - b * 200;
                    int half = cb >> 7, jj = cb & 127;
                    __half* base = ht + (size_t)half * HT_HALF + (size_t)b * 25600;
                    base[jj * 200 + i]       = __float2half_rn(v0);
                    base[(jj + 1) * 200 + i] = __float2half_rn(v1);
                } else {
                    *(uint32_t*)(Ch + (size_t)gm * ldc + (cb - cshift)) = pack_h2(v0, v1);
                }
            }
        }
    }
}

// ---------------------------------------------------------------------------
// fp16 GEMM (stage 4): block 128x128, K-chunk 32 (2 x k16), 3-stage cp.async.
// A = f32 adjacency in smem (LDPA=40 pad), cvt f32x2->h2 at frag load.
// B = ht fp16 in smem (LDPB=40). Output: tf32-rounded f32 inputs.
// grid (2, 2, 512): x = half, y = m-tile, z = batch. K=200, no mainloop guards.
// ---------------------------------------------------------------------------
#define LDPA 40
#define LDPB 40
#define A4_F (128 * LDPA)                 // floats
#define B4_H (128 * LDPB)                 // halfs
#define STAGE4_B (A4_F * 4 + B4_H * 2)    // 30720 B
#define SMEM4 (3 * STAGE4_B)              // 92160 B

__device__ __forceinline__ void load_stage4(uint32_t sb, const float* __restrict__ A,
                                            int a_rows, const __half* __restrict__ B,
                                            int k0, int tid) {
    #pragma unroll
    for (int it = 0; it < 4; ++it) {
        int item = it * 256 + tid;
        int row = item >> 3, c4 = item & 7;
        int gk = k0 + c4 * 4;
        bool ok = (row < a_rows) && (gk < Nn);
        const float* src = ok ? (A + (long long)row * (2 * Nn) + gk) : A;
        CP_ASYNC(sb + (uint32_t)(row * LDPA + c4 * 4) * 4, src, ok ? 16 : 0);
    }
    #pragma unroll
    for (int it = 0; it < 2; ++it) {
        int item = it * 256 + tid;
        int row = item >> 2, c8 = item & 3;
        int gk = k0 + c8 * 8;
        bool ok = (gk < Nn);
        const __half* src = ok ? (B + (size_t)row * Nn + gk) : B;
        CP_ASYNC(sb + (uint32_t)A4_F * 4 + (uint32_t)(row * LDPB + c8 * 8) * 2, src, ok ? 16 : 0);
    }
}

__global__ __launch_bounds__(256, 2)
void hgemm4(const float* __restrict__ Amat, const __half* __restrict__ Bht,
            const float* __restrict__ biasA, const float* __restrict__ biasB,
            float* __restrict__ Cf) {
    extern __shared__ float smemf[];
    const uint32_t sbase = smem_u32(smemf);
    const int tid = threadIdx.x;
    const int wid = tid >> 5, lane = tid & 31;
    const int gid = lane >> 2, tig = lane & 3;
    const int wm0 = (wid >> 2) * 64;
    const int wn0 = (wid & 3) * 32;

    const int half = blockIdx.x;
    const int m0 = blockIdx.y * 128;
    const float* A = Amat + (long long)blockIdx.z * (Nn * 2 * Nn) + half * Nn
                   + (long long)m0 * (2 * Nn);
    const __half* Bm = Bht + (size_t)half * HT_HALF + (size_t)blockIdx.z * 25600;
    const float* bias = half ? biasB : biasA;
    float* Cb = Cf + (long long)blockIdx.z * ((long long)Nn * 256) + half * 128;
    const int a_rows = (Nn - m0) < 128 ? (Nn - m0) : 128;    // 128 or 72

    float acc[4][4][4];
    #pragma unroll
    for (int i = 0; i < 4; ++i)
        #pragma unroll
        for (int j = 0; j < 4; ++j)
            #pragma unroll
            for (int q = 0; q < 4; ++q) acc[i][j][q] = 0.f;

    const int nk = (Nn + 31) / 32;        // 7
    load_stage4(sbase, A, a_rows, Bm, 0, tid);
    CP_COMMIT();
    load_stage4(sbase + (uint32_t)STAGE4_B, A, a_rows, Bm, 32, tid);
    CP_COMMIT();

    int buf = 0;
    for (int ck = 0; ck < nk; ++ck) {
        if (ck + 2 < nk) {
            int nbuf = (buf + 2 >= 3) ? buf - 1 : buf + 2;
            load_stage4(sbase + (uint32_t)nbuf * STAGE4_B, A, a_rows, Bm, (ck + 2) * 32, tid);
            CP_COMMIT();
            CP_WAIT(2);
        } else if (ck + 1 < nk) {
            CP_WAIT(1);
        } else {
            CP_WAIT(0);
        }
        __syncthreads();

        const float*  As_f = (const float*)((const char*)smemf + buf * STAGE4_B);
        const __half* Bs_h = (const __half*)((const char*)As_f + A4_F * 4);

        #pragma unroll
        for (int ks = 0; ks < 2; ++ks) {
            uint32_t af[4][4], bf[4][2];
            #pragma unroll
            for (int tm = 0; tm < 4; ++tm) {
                const float* p = As_f + (wm0 + tm * 16 + gid) * LDPA + ks * 16 + tig * 2;
                float2 v0 = *(const float2*)(p);
                float2 v1 = *(const float2*)(p + 8 * LDPA);
                float2 v2 = *(const float2*)(p + 8);
                float2 v3 = *(const float2*)(p + 8 * LDPA + 8);
                af[tm][0] = pack_h2(v0.x, v0.y);
                af[tm][1] = pack_h2(v1.x, v1.y);
                af[tm][2] = pack_h2(v2.x, v2.y);
                af[tm][3] = pack_h2(v3.x, v3.y);
            }
            #pragma unroll
            for (int tn = 0; tn < 4; ++tn) {
                const __half* p = Bs_h + (wn0 + tn * 8 + gid) * LDPB + ks * 16 + tig * 2;
                bf[tn][0] = *(const uint32_t*)p;
                bf[tn][1] = *(const uint32_t*)(p + 8);
            }
            #pragma unroll
            for (int tm = 0; tm < 4; ++tm)
                #pragma unroll
                for (int tn = 0; tn < 4; ++tn)
                    mma16(acc[tm][tn], af[tm], bf[tn]);
        }
        __syncthreads();
        buf = (buf + 1 >= 3) ? 0 : buf + 1;
    }

    // ---- epilogue: tf32-rounded f32 store into inputs ----
    #pragma unroll
    for (int tm = 0; tm < 4; ++tm) {
        #pragma unroll
        for (int half_m = 0; half_m < 2; ++half_m) {
            const int gml = wm0 + tm * 16 + gid + half_m * 8;
            if (gml >= a_rows) continue;
            const int gm = m0 + gml;
            #pragma unroll
            for (int tn = 0; tn < 4; ++tn) {
                const int cb = wn0 + tn * 8 + tig * 2;
                float v0 = acc[tm][tn][half_m * 2 + 0] + bias[cb];
                float v1 = acc[tm][tn][half_m * 2 + 1] + bias[cb + 1];
                *(float2*)(Cb + (size_t)gm * 256 + cb) =
                    make_float2(round_tf32(v0), round_tf32(v1));
            }
        }
    }
}

// ---------------- gates (fp16 gi/gh, 2 elems/thread) ----------------
__global__ void gates_kernel(float* __restrict__ out) {
    long long idx = (long long)blockIdx.x * blockDim.x + threadIdx.x;
    const long long total = (long long)Mrows * 64;
    if (idx >= total) return;
    int row = (int)(idx >> 6);
    int p   = (int)(idx & 63);

    const __half2* gi = (const __half2*)(g_gi_h + (size_t)row * 384);
    const __half2* gh = (const __half2*)(g_gh_h + (size_t)row * 384);
    float2 i_r = __half22float2(gi[p]);
    float2 i_i = __half22float2(gi[64 + p]);
    float2 i_n = __half22float2(gi[128 + p]);
    float2 h_r = __half22float2(gh[p]);
    float2 h_i = __half22float2(gh[64 + p]);
    float2 h_n = __half22float2(gh[128 + p]);
    float2 hid = ((const float2*)(g_hidden + (size_t)row * 128))[p];

    float2 o;
    {
        float gin = 1.f / (1.f + expf(-(i_i.x + h_i.x)));
        float grs = 1.f / (1.f + expf(-(i_r.x + h_r.x)));
        float got = tanhf(i_n.x + grs * h_n.x);
        o.x = got + gin * (hid.x - got);
    }
    {
        float gin = 1.f / (1.f + expf(-(i_i.y + h_i.y)));
        float grs = 1.f / (1.f + expf(-(i_r.y + h_r.y)));
        float got = tanhf(i_n.y + grs * h_n.y);
        o.y = got + gin * (hid.y - got);
    }
    ((float2*)(out + (size_t)row * 128))[p] = o;
}

// ---------------------------------------------------------------------------
extern "C" void kernel_launch(void* const* d_in, const int* in_sizes, int n_in,
                              void* d_out, int out_size) {
    const int*   x     = (const int*)  d_in[0];
    const float* Amat  = (const float*)d_in[1];
    const float* emb   = (const float*)d_in[2];
    const float* w_in  = (const float*)d_in[3];
    const float* b_in  = (const float*)d_in[4];
    const float* w_out = (const float*)d_in[5];
    const float* b_out = (const float*)d_in[6];
    const float* w_ih  = (const float*)d_in[7];
    const float* b_ih  = (const float*)d_in[8];
    const float* w_hh  = (const float*)d_in[9];
    const float* b_hh  = (const float*)d_in[10];
    const float* b_iah = (const float*)d_in[11];
    const float* b_oah = (const float*)d_in[12];
    float* out = (float*)d_out;

    void *p_hidden_r, *p_ht_h, *p_gh_h, *p_inputs, *p_gi_h, *p_W1, *p_W2r, *p_bias1;
    cudaGetSymbolAddress(&p_hidden_r, g_hidden_r);
    cudaGetSymbolAddress(&p_ht_h,   g_ht_h);
    cudaGetSymbolAddress(&p_gh_h,   g_gh_h);
    cudaGetSymbolAddress(&p_inputs, g_inputs);
    cudaGetSymbolAddress(&p_gi_h,   g_gi_h);
    cudaGetSymbolAddress(&p_W1,     g_W1);
    cudaGetSymbolAddress(&p_W2r,    g_W2r);
    cudaGetSymbolAddress(&p_bias1,  g_bias1);

    cudaFuncSetAttribute(mma_gemm<0>, cudaFuncAttributeMaxDynamicSharedMemorySize, SMEM_BYTES);
    cudaFuncSetAttribute(mma_gemm<1>, cudaFuncAttributeMaxDynamicSharedMemorySize, SMEM_BYTES);
    cudaFuncSetAttribute(hgemm4,      cudaFuncAttributeMaxDynamicSharedMemorySize, SMEM4);

    // 1. prep
    {
        int total = 640 * 128 + 384 * 256 + 640;
        prep_kernel<<<(total + 255) / 256, 256>>>(w_in, b_in, w_out, b_out, w_ih, w_hh, b_hh);
    }
    // 2. gather
    {
        long long total4 = (long long)Mrows * 32;
        gather_kernel<<<(int)((total4 + 255) / 256), 256>>>(x, emb);
    }
    // 3. big = hidden_r @ W1^T + bias1  (n<256 -> ht fp16 transposed; else gh fp16)
    mma_gemm<1><<<dim3(5, Mrows / 128, 1), 256, SMEM_BYTES>>>(
        (const float*)p_hidden_r, 128, Mrows,
        (const float*)p_W1, 128,
        (const float*)p_bias1,
        (__half*)p_gh_h, 384, 256,
        (__half*)p_ht_h, 128);
    // 4. inputs = [A_lo@h_in + b_iah | A_hi@h_out + b_oah]  (fp16 MMA, f32 out)
    hgemm4<<<dim3(2, 2, Bsz), 256, SMEM4>>>(
        Amat, (const __half*)p_ht_h, b_iah, b_oah, (float*)p_inputs);
    // 5. gi = inputs @ w_ih^T + b_ih  (fp16 store)
    mma_gemm<0><<<dim3(3, Mrows / 128, 1), 256, SMEM_BYTES>>>(
        (const float*)p_inputs, 256, Mrows,
        (const float*)p_W2r, 256,
        b_ih,
        (__half*)p_gi_h, 384, 0,
        nullptr, 256);
    // 6. gates
    {
        long long total = (long long)Mrows * 64;
        gates_kernel<<<(int)((total + 255) / 256), 256>>>(out);
    }
}

// round 17
// speedup vs baseline: 1.8104x; 1.3205x over previous
#include <cuda_runtime.h>
#include <cuda_fp16.h>
#include <cstdint>

// ---------------------------------------------------------------------------
// SR_GNN, fp16 end-to-end intermediates (fp16 mantissa == tf32 mantissa).
//   hidden_h = fp16(emb[x])
//   stage3 (fp16 MMA): big = hidden_h @ W1h^T + bias
//            cols<256 -> ht fp16 (transposed per batch); cols>=256 -> gh fp16
//   stage4 (fp16 MMA, A=f32 adjacency cvt at frag load):
//            inputs_h = [A_lo@h_in+b_iah | A_hi@h_out+b_oah]   fp16
//   stage5 (fp16 MMA): gi = inputs_h @ W2h^T + b_ih            fp16
//   gates(gi, gh, hidden_h) -> f32 out
// ---------------------------------------------------------------------------

#define Bsz 512
#define Nn  200
#define Mrows (Bsz*Nn)                 // 102400
#define HT_HALF (512*128*200)

__device__ __half g_hidden_h[(size_t)Mrows * 128];
__device__ __half g_ht_h    [(size_t)2 * HT_HALF];
__device__ __half g_gh_h    [(size_t)Mrows * 384];
__device__ __half g_inputs_h[(size_t)Mrows * 256];
__device__ __half g_gi_h    [(size_t)Mrows * 384];
__device__ __half g_W1h     [640 * 128];
__device__ __half g_W2h     [384 * 256];
__device__ float  g_bias1   [640];

// ---------------- helpers ----------------
__device__ __forceinline__ uint32_t smem_u32(const void* p) {
    uint32_t a;
    asm("{ .reg .u64 t; cvta.to.shared.u64 t, %1; cvt.u32.u64 %0, t; }" : "=r"(a) : "l"(p));
    return a;
}
__device__ __forceinline__ uint32_t pack_h2(float lo, float hi) {
    __half2 h = __floats2half2_rn(lo, hi);
    return *(uint32_t*)&h;
}
__device__ __forceinline__ void mma16(float* d, const uint32_t* a, const uint32_t* b) {
    asm volatile("mma.sync.aligned.m16n8k16.row.col.f32.f16.f16.f32 "
        "{%0,%1,%2,%3}, {%4,%5,%6,%7}, {%8,%9}, {%0,%1,%2,%3};"
        : "+f"(d[0]), "+f"(d[1]), "+f"(d[2]), "+f"(d[3])
        : "r"(a[0]), "r"(a[1]), "r"(a[2]), "r"(a[3]), "r"(b[0]), "r"(b[1]));
}
#define CP_ASYNC(dst, src, sz) \
    asm volatile("cp.async.cg.shared.global [%0], [%1], 16, %2;" :: "r"(dst), "l"(src), "r"(sz))
#define CP_COMMIT()  asm volatile("cp.async.commit_group;" ::: "memory")
#define CP_WAIT(n)   asm volatile("cp.async.wait_group %0;" :: "n"(n) : "memory")

// ---------------- prep / gather ----------------
__global__ void prep_kernel(const float* __restrict__ w_in, const float* __restrict__ b_in,
                            const float* __restrict__ w_out, const float* __restrict__ b_out,
                            const float* __restrict__ w_ih,
                            const float* __restrict__ w_hh, const float* __restrict__ b_hh) {
    int idx = blockIdx.x * blockDim.x + threadIdx.x;
    if (idx < 640 * 128) {
        int j = idx / 128, k = idx % 128;
        float v;
        if (j < 128)      v = w_in [j * 128 + k];
        else if (j < 256) v = w_out[(j - 128) * 128 + k];
        else              v = w_hh [(j - 256) * 128 + k];
        g_W1h[idx] = __float2half_rn(v);
    } else if (idx < 640 * 128 + 384 * 256) {
        int t = idx - 640 * 128;
        g_W2h[t] = __float2half_rn(w_ih[t]);
    } else if (idx < 640 * 128 + 384 * 256 + 640) {
        int j = idx - 640 * 128 - 384 * 256;
        g_bias1[j] = (j < 128) ? b_in[j] : (j < 256) ? b_out[j - 128] : b_hh[j - 256];
    }
}

__global__ void gather_kernel(const int* __restrict__ x, const float* __restrict__ emb) {
    long long t = (long long)blockIdx.x * blockDim.x + threadIdx.x;
    const long long total4 = (long long)Mrows * 32;
    if (t >= total4) return;
    int m = (int)(t >> 5), c = (int)(t & 31);
    int v = __ldg(&x[m]);
    float4 e = ((const float4*)emb)[(long long)v * 32 + c];
    __half2 h01 = __floats2half2_rn(e.x, e.y);
    __half2 h23 = __floats2half2_rn(e.z, e.w);
    ((__half2*)g_hidden_h)[t * 2]     = h01;
    ((__half2*)g_hidden_h)[t * 2 + 1] = h23;
}

// ---------------------------------------------------------------------------
// fp16 GEMM (stages 3 & 5): block 128x128, K-chunk 32 (2 x k16), 4-stage
// cp.async, 8 warps (2x4), warp tile 64x32. Guard-free (dims exact).
// MODE 1: stage3 (n<256 -> ht fp16 transposed per batch; else gh fp16)
// MODE 0: stage5 (fp16 store to gi)
// ---------------------------------------------------------------------------
#define LDP2 40
#define ATILE_H (128 * LDP2)
#define STAGE_H (2 * ATILE_H)            // 10240 halfs = 20480 B
#define SMEM_BYTES_H (4 * STAGE_H * 2)   // 81920 B

__device__ __forceinline__ void load_stage_h(uint32_t sb, const __half* __restrict__ A, int lda,
                                             const __half* __restrict__ B, int ldb,
                                             int k0, int tid) {
    #pragma unroll
    for (int it = 0; it < 2; ++it) {
        int item = it * 256 + tid;
        int row = item >> 2, c8 = item & 3;
        CP_ASYNC(sb + (uint32_t)(row * LDP2 + c8 * 8) * 2,
                 A + (size_t)row * lda + k0 + c8 * 8, 16);
    }
    #pragma unroll
    for (int it = 0; it < 2; ++it) {
        int item = it * 256 + tid;
        int row = item >> 2, c8 = item & 3;
        CP_ASYNC(sb + (uint32_t)(ATILE_H + row * LDP2 + c8 * 8) * 2,
                 B + (size_t)row * ldb + k0 + c8 * 8, 16);
    }
}

template <int MODE>
__global__ __launch_bounds__(256, 2)
void hgemm(const __half* __restrict__ A, int lda,
           const __half* __restrict__ Bm, int ldb,
           const float* __restrict__ bias,
           __half* __restrict__ Ch, int ldc, int cshift,
           __half* __restrict__ ht, int K) {
    extern __shared__ __half smemh[];
    const uint32_t sbase = smem_u32(smemh);
    const int tid = threadIdx.x;
    const int wid = tid >> 5, lane = tid & 31;
    const int gid = lane >> 2, tig = lane & 3;
    const int wm0 = (wid >> 2) * 64;
    const int wn0 = (wid & 3) * 32;

    const int n0 = blockIdx.x * 128;
    const int m0 = blockIdx.y * 128;
    const __half* Asrc = A + (size_t)m0 * lda;
    const __half* Bsrc = Bm + (size_t)n0 * ldb;

    float acc[4][4][4];
    #pragma unroll
    for (int i = 0; i < 4; ++i)
        #pragma unroll
        for (int j = 0; j < 4; ++j)
            #pragma unroll
            for (int q = 0; q < 4; ++q) acc[i][j][q] = 0.f;

    const int nk = K / 32;                       // 4 or 8
    load_stage_h(sbase, Asrc, lda, Bsrc, ldb, 0, tid);
    CP_COMMIT();
    load_stage_h(sbase + (uint32_t)STAGE_H * 2, Asrc, lda, Bsrc, ldb, 32, tid);
    CP_COMMIT();
    load_stage_h(sbase + (uint32_t)2 * STAGE_H * 2, Asrc, lda, Bsrc, ldb, 64, tid);
    CP_COMMIT();
    CP_WAIT(2);
    __syncthreads();

    for (int ck = 0; ck < nk; ++ck) {
        if (ck + 3 < nk) {
            load_stage_h(sbase + (uint32_t)((ck + 3) & 3) * STAGE_H * 2,
                         Asrc, lda, Bsrc, ldb, (ck + 3) * 32, tid);
            CP_COMMIT();
        }
        const __half* As = smemh + (ck & 3) * STAGE_H;
        const __half* Bs = As + ATILE_H;

        #pragma unroll
        for (int ks = 0; ks < 2; ++ks) {
            uint32_t af[4][4], bf[4][2];
            #pragma unroll
            for (int tm = 0; tm < 4; ++tm) {
                const __half* p = As + (wm0 + tm * 16 + gid) * LDP2 + ks * 16 + tig * 2;
                af[tm][0] = *(const uint32_t*)p;
                af[tm][1] = *(const uint32_t*)(p + 8 * LDP2);
                af[tm][2] = *(const uint32_t*)(p + 8);
                af[tm][3] = *(const uint32_t*)(p + 8 * LDP2 + 8);
            }
            #pragma unroll
            for (int tn = 0; tn < 4; ++tn) {
                const __half* p = Bs + (wn0 + tn * 8 + gid) * LDP2 + ks * 16 + tig * 2;
                bf[tn][0] = *(const uint32_t*)p;
                bf[tn][1] = *(const uint32_t*)(p + 8);
            }
            #pragma unroll
            for (int tm = 0; tm < 4; ++tm)
                #pragma unroll
                for (int tn = 0; tn < 4; ++tn)
                    mma16(acc[tm][tn], af[tm], bf[tn]);
        }

        if (ck + 3 < nk) { CP_WAIT(2); } else if (ck + 2 < nk) { CP_WAIT(1); } else { CP_WAIT(0); }
        __syncthreads();
    }

    // ---- epilogue ----
    #pragma unroll
    for (int tm = 0; tm < 4; ++tm) {
        #pragma unroll
        for (int half_m = 0; half_m < 2; ++half_m) {
            const int gm = m0 + wm0 + tm * 16 + gid + half_m * 8;
            #pragma unroll
            for (int tn = 0; tn < 4; ++tn) {
                const int cb = n0 + wn0 + tn * 8 + tig * 2;
                float v0 = acc[tm][tn][half_m * 2 + 0] + bias[cb];
                float v1 = acc[tm][tn][half_m * 2 + 1] + bias[cb + 1];
                if (MODE == 1 && n0 < 256) {
                    int b = gm / 200, i = gm - b * 200;
                    int half = cb >> 7, jj = cb & 127;
                    __half* base = ht + (size_t)half * HT_HALF + (size_t)b * 25600;
                    base[jj * 200 + i]       = __float2half_rn(v0);
                    base[(jj + 1) * 200 + i] = __float2half_rn(v1);
                } else {
                    *(uint32_t*)(Ch + (size_t)gm * ldc + (cb - cshift)) = pack_h2(v0, v1);
                }
            }
        }
    }
}

// ---------------------------------------------------------------------------
// fp16 GEMM (stage 4): as R16 (proven 82us) but fp16 output to inputs_h.
// A = f32 adjacency in smem (LDPA=40), cvt f32x2->h2 at frag load.
// B = ht fp16 (LDPB=40). grid (2, 2, 512). K=200, no mainloop guards.
// ---------------------------------------------------------------------------
#define LDPA 40
#define LDPB 40
#define A4_F (128 * LDPA)
#define B4_H (128 * LDPB)
#define STAGE4_B (A4_F * 4 + B4_H * 2)    // 30720 B
#define SMEM4 (3 * STAGE4_B)              // 92160 B

__device__ __forceinline__ void load_stage4(uint32_t sb, const float* __restrict__ A,
                                            int a_rows, const __half* __restrict__ B,
                                            int k0, int tid) {
    #pragma unroll
    for (int it = 0; it < 4; ++it) {
        int item = it * 256 + tid;
        int row = item >> 3, c4 = item & 7;
        int gk = k0 + c4 * 4;
        bool ok = (row < a_rows) && (gk < Nn);
        const float* src = ok ? (A + (long long)row * (2 * Nn) + gk) : A;
        CP_ASYNC(sb + (uint32_t)(row * LDPA + c4 * 4) * 4, src, ok ? 16 : 0);
    }
    #pragma unroll
    for (int it = 0; it < 2; ++it) {
        int item = it * 256 + tid;
        int row = item >> 2, c8 = item & 3;
        int gk = k0 + c8 * 8;
        bool ok = (gk < Nn);
        const __half* src = ok ? (B + (size_t)row * Nn + gk) : B;
        CP_ASYNC(sb + (uint32_t)A4_F * 4 + (uint32_t)(row * LDPB + c8 * 8) * 2, src, ok ? 16 : 0);
    }
}

__global__ __launch_bounds__(256, 2)
void hgemm4(const float* __restrict__ Amat, const __half* __restrict__ Bht,
            const float* __restrict__ biasA, const float* __restrict__ biasB,
            __half* __restrict__ Ch) {
    extern __shared__ float smemf[];
    const uint32_t sbase = smem_u32(smemf);
    const int tid = threadIdx.x;
    const int wid = tid >> 5, lane = tid & 31;
    const int gid = lane >> 2, tig = lane & 3;
    const int wm0 = (wid >> 2) * 64;
    const int wn0 = (wid & 3) * 32;

    const int half = blockIdx.x;
    const int m0 = blockIdx.y * 128;
    const float* A = Amat + (long long)blockIdx.z * (Nn * 2 * Nn) + half * Nn
                   + (long long)m0 * (2 * Nn);
    const __half* Bm = Bht + (size_t)half * HT_HALF + (size_t)blockIdx.z * 25600;
    const float* bias = half ? biasB : biasA;
    __half* Cb = Ch + (long long)blockIdx.z * ((long long)Nn * 256) + half * 128;
    const int a_rows = (Nn - m0) < 128 ? (Nn - m0) : 128;    // 128 or 72

    float acc[4][4][4];
    #pragma unroll
    for (int i = 0; i < 4; ++i)
        #pragma unroll
        for (int j = 0; j < 4; ++j)
            #pragma unroll
            for (int q = 0; q < 4; ++q) acc[i][j][q] = 0.f;

    const int nk = (Nn + 31) / 32;        // 7
    load_stage4(sbase, A, a_rows, Bm, 0, tid);
    CP_COMMIT();
    load_stage4(sbase + (uint32_t)STAGE4_B, A, a_rows, Bm, 32, tid);
    CP_COMMIT();

    int buf = 0;
    for (int ck = 0; ck < nk; ++ck) {
        if (ck + 2 < nk) {
            int nbuf = (buf + 2 >= 3) ? buf - 1 : buf + 2;
            load_stage4(sbase + (uint32_t)nbuf * STAGE4_B, A, a_rows, Bm, (ck + 2) * 32, tid);
            CP_COMMIT();
            CP_WAIT(2);
        } else if (ck + 1 < nk) {
            CP_WAIT(1);
        } else {
            CP_WAIT(0);
        }
        __syncthreads();

        const float*  As_f = (const float*)((const char*)smemf + buf * STAGE4_B);
        const __half* Bs_h = (const __half*)((const char*)As_f + A4_F * 4);

        #pragma unroll
        for (int ks = 0; ks < 2; ++ks) {
            uint32_t af[4][4], bf[4][2];
            #pragma unroll
            for (int tm = 0; tm < 4; ++tm) {
                const float* p = As_f + (wm0 + tm * 16 + gid) * LDPA + ks * 16 + tig * 2;
                float2 v0 = *(const float2*)(p);
                float2 v1 = *(const float2*)(p + 8 * LDPA);
                float2 v2 = *(const float2*)(p + 8);
                float2 v3 = *(const float2*)(p + 8 * LDPA + 8);
                af[tm][0] = pack_h2(v0.x, v0.y);
                af[tm][1] = pack_h2(v1.x, v1.y);
                af[tm][2] = pack_h2(v2.x, v2.y);
                af[tm][3] = pack_h2(v3.x, v3.y);
            }
            #pragma unroll
            for (int tn = 0; tn < 4; ++tn) {
                const __half* p = Bs_h + (wn0 + tn * 8 + gid) * LDPB + ks * 16 + tig * 2;
                bf[tn][0] = *(const uint32_t*)p;
                bf[tn][1] = *(const uint32_t*)(p + 8);
            }
            #pragma unroll
            for (int tm = 0; tm < 4; ++tm)
                #pragma unroll
                for (int tn = 0; tn < 4; ++tn)
                    mma16(acc[tm][tn], af[tm], bf[tn]);
        }
        __syncthreads();
        buf = (buf + 1 >= 3) ? 0 : buf + 1;
    }

    // ---- epilogue: fp16 store into inputs_h ----
    #pragma unroll
    for (int tm = 0; tm < 4; ++tm) {
        #pragma unroll
        for (int half_m = 0; half_m < 2; ++half_m) {
            const int gml = wm0 + tm * 16 + gid + half_m * 8;
            if (gml >= a_rows) continue;
            const int gm = m0 + gml;
            #pragma unroll
            for (int tn = 0; tn < 4; ++tn) {
                const int cb = wn0 + tn * 8 + tig * 2;
                float v0 = acc[tm][tn][half_m * 2 + 0] + bias[cb];
                float v1 = acc[tm][tn][half_m * 2 + 1] + bias[cb + 1];
                *(uint32_t*)(Cb + (size_t)gm * 256 + cb) = pack_h2(v0, v1);
            }
        }
    }
}

// ---------------- gates (all-fp16 inputs, 2 elems/thread) ----------------
__global__ void gates_kernel(float* __restrict__ out) {
    long long idx = (long long)blockIdx.x * blockDim.x + threadIdx.x;
    const long long total = (long long)Mrows * 64;
    if (idx >= total) return;
    int row = (int)(idx >> 6);
    int p   = (int)(idx & 63);

    const __half2* gi = (const __half2*)(g_gi_h + (size_t)row * 384);
    const __half2* gh = (const __half2*)(g_gh_h + (size_t)row * 384);
    float2 i_r = __half22float2(gi[p]);
    float2 i_i = __half22float2(gi[64 + p]);
    float2 i_n = __half22float2(gi[128 + p]);
    float2 h_r = __half22float2(gh[p]);
    float2 h_i = __half22float2(gh[64 + p]);
    float2 h_n = __half22float2(gh[128 + p]);
    float2 hid = __half22float2(((const __half2*)(g_hidden_h + (size_t)row * 128))[p]);

    float2 o;
    {
        float gin = 1.f / (1.f + expf(-(i_i.x + h_i.x)));
        float grs = 1.f / (1.f + expf(-(i_r.x + h_r.x)));
        float got = tanhf(i_n.x + grs * h_n.x);
        o.x = got + gin * (hid.x - got);
    }
    {
        float gin = 1.f / (1.f + expf(-(i_i.y + h_i.y)));
        float grs = 1.f / (1.f + expf(-(i_r.y + h_r.y)));
        float got = tanhf(i_n.y + grs * h_n.y);
        o.y = got + gin * (hid.y - got);
    }
    ((float2*)(out + (size_t)row * 128))[p] = o;
}

// ---------------------------------------------------------------------------
extern "C" void kernel_launch(void* const* d_in, const int* in_sizes, int n_in,
                              void* d_out, int out_size) {
    const int*   x     = (const int*)  d_in[0];
    const float* Amat  = (const float*)d_in[1];
    const float* emb   = (const float*)d_in[2];
    const float* w_in  = (const float*)d_in[3];
    const float* b_in  = (const float*)d_in[4];
    const float* w_out = (const float*)d_in[5];
    const float* b_out = (const float*)d_in[6];
    const float* w_ih  = (const float*)d_in[7];
    const float* b_ih  = (const float*)d_in[8];
    const float* w_hh  = (const float*)d_in[9];
    const float* b_hh  = (const float*)d_in[10];
    const float* b_iah = (const float*)d_in[11];
    const float* b_oah = (const float*)d_in[12];
    float* out = (float*)d_out;

    void *p_hidden_h, *p_ht_h, *p_gh_h, *p_inputs_h, *p_gi_h, *p_W1h, *p_W2h, *p_bias1;
    cudaGetSymbolAddress(&p_hidden_h, g_hidden_h);
    cudaGetSymbolAddress(&p_ht_h,     g_ht_h);
    cudaGetSymbolAddress(&p_gh_h,     g_gh_h);
    cudaGetSymbolAddress(&p_inputs_h, g_inputs_h);
    cudaGetSymbolAddress(&p_gi_h,     g_gi_h);
    cudaGetSymbolAddress(&p_W1h,      g_W1h);
    cudaGetSymbolAddress(&p_W2h,      g_W2h);
    cudaGetSymbolAddress(&p_bias1,    g_bias1);

    cudaFuncSetAttribute(hgemm<0>, cudaFuncAttributeMaxDynamicSharedMemorySize, SMEM_BYTES_H);
    cudaFuncSetAttribute(hgemm<1>, cudaFuncAttributeMaxDynamicSharedMemorySize, SMEM_BYTES_H);
    cudaFuncSetAttribute(hgemm4,   cudaFuncAttributeMaxDynamicSharedMemorySize, SMEM4);

    // 1. prep (fp16 weights)
    {
        int total = 640 * 128 + 384 * 256 + 640;
        prep_kernel<<<(total + 255) / 256, 256>>>(w_in, b_in, w_out, b_out, w_ih, w_hh, b_hh);
    }
    // 2. gather (fp16 hidden only)
    {
        long long total4 = (long long)Mrows * 32;
        gather_kernel<<<(int)((total4 + 255) / 256), 256>>>(x, emb);
    }
    // 3. big = hidden_h @ W1h^T + bias1  (n<256 -> ht fp16; else gh fp16)
    hgemm<1><<<dim3(5, Mrows / 128, 1), 256, SMEM_BYTES_H>>>(
        (const __half*)p_hidden_h, 128,
        (const __half*)p_W1h, 128,
        (const float*)p_bias1,
        (__half*)p_gh_h, 384, 256,
        (__half*)p_ht_h, 128);
    // 4. inputs_h = [A_lo@h_in + b_iah | A_hi@h_out + b_oah]  (fp16 out)
    hgemm4<<<dim3(2, 2, Bsz), 256, SMEM4>>>(
        Amat, (const __half*)p_ht_h, b_iah, b_oah, (__half*)p_inputs_h);
    // 5. gi = inputs_h @ W2h^T + b_ih  (fp16)
    hgemm<0><<<dim3(3, Mrows / 128, 1), 256, SMEM_BYTES_H>>>(
        (const __half*)p_inputs_h, 256,
        (const __half*)p_W2h, 256,
        b_ih,
        (__half*)p_gi_h, 384, 0,
        nullptr, 256);
    // 6. gates
    {
        long long total = (long long)Mrows * 64;
        gates_kernel<<<(int)((total + 255) / 256), 256>>>(out);
    }
}